// round 2
// baseline (speedup 1.0000x reference)
#include <cuda_runtime.h>

#define TOTPTS 16384
#define NPTS   4096
#define KNN    16
#define PAD    132                     // H-buffer row stride (floats), 128 edges + pad
#define NGROUPS (TOTPTS / 8)           // 2048 groups of 8 points

#define MAIN_W_FLOATS   24576          // Ws2(64x64) + Ws3(128x64) + Ws4(192x64)
#define MAIN_H_FLOATS   (192 * PAD)    // H3|H2|H1 transposed, each 64 rows x 128 edges
#define MAIN_SMEM_BYTES ((MAIN_W_FLOATS + MAIN_H_FLOATS) * 4 + 128 * 4)

// Scratch (allocation-free rule: device globals)
__device__ __align__(16) float g_L[TOTPTS * 256];   // [P | R1 | R2 | R3] per point
__device__ __align__(16) float g_Q[TOTPTS * 64];    // Q per point
__device__ int g_idx[TOTPTS * KNN];

// ---------------------------------------------------------------------------
// KNN: one thread per query point; smem-tiled candidates; replace-max top-16.
// d2 computed with the same expansion formula as the reference (ni + nj - 2*dot)
// so ordering near ties matches. Self excluded explicitly (reference drops col 0).
// ---------------------------------------------------------------------------
__global__ __launch_bounds__(128) void knn_kernel(const float* __restrict__ pos) {
    int b = blockIdx.x >> 5;                       // 32 blocks per batch
    int q = ((blockIdx.x & 31) << 7) + threadIdx.x;
    const float* pb = pos + b * NPTS * 3;
    float qx = __ldg(pb + q * 3 + 0);
    float qy = __ldg(pb + q * 3 + 1);
    float qz = __ldg(pb + q * 3 + 2);
    float qn = qx * qx + qy * qy + qz * qz;

    __shared__ float4 sp[128];

    float dv[KNN];
    int   iv[KNN];
#pragma unroll
    for (int r = 0; r < KNN; r++) { dv[r] = 3.0e38f; iv[r] = 0; }
    float dmax = 3.0e38f;
    int   amax = 0;

    for (int t0 = 0; t0 < NPTS; t0 += 128) {
        __syncthreads();
        {
            int j = t0 + threadIdx.x;
            float x = pb[j * 3 + 0], y = pb[j * 3 + 1], z = pb[j * 3 + 2];
            sp[threadIdx.x] = make_float4(x, y, z, x * x + y * y + z * z);
        }
        __syncthreads();
#pragma unroll 4
        for (int jj = 0; jj < 128; jj++) {
            float4 c = sp[jj];
            float dot = qx * c.x;
            dot = fmaf(qy, c.y, dot);
            dot = fmaf(qz, c.z, dot);
            float d2 = qn + c.w - 2.0f * dot;
            int jg = t0 + jj;
            if (d2 < dmax && jg != q) {
                dv[amax] = d2; iv[amax] = jg;
                dmax = dv[0]; amax = 0;
#pragma unroll
                for (int r = 1; r < KNN; r++)
                    if (dv[r] > dmax) { dmax = dv[r]; amax = r; }
            }
        }
    }
    int base = (b * NPTS + q) * KNN;
#pragma unroll
    for (int r = 0; r < KNN; r++) g_idx[base + r] = iv[r];
}

// ---------------------------------------------------------------------------
// Per-point precompute: [P,Q,R1,R2,R3] = x @ combined 64x320 weight (+biases).
//   P  = x@(Wa - Wc) + b_first      (Wa = W_first rows 0:64, Wc = rows 128:192)
//   Q  = x@(Wb + Wc)                (Wb = rows 64:128)
//   R1 = x@W_mid1[64:128]  + b_mid1
//   R2 = x@W_mid2[128:192] + b_mid2
//   R3 = x@W_last[192:256] + b_last
// Tiled GEMM: 64 points per block, one 64-wide section at a time.
// ---------------------------------------------------------------------------
__global__ __launch_bounds__(256) void pre_kernel(
    const float* __restrict__ x,
    const float* __restrict__ Wf,  const float* __restrict__ bf,
    const float* __restrict__ Wm1, const float* __restrict__ bm1,
    const float* __restrict__ Wm2, const float* __restrict__ bm2,
    const float* __restrict__ Wl,  const float* __restrict__ bl) {

    __shared__ float sw[4096];        // current section weights 64x64
    __shared__ float sx[64 * 68];     // x tile transposed: sx[k][m], padded

    int t   = threadIdx.x;
    int pt0 = blockIdx.x * 64;

    for (int i = t; i < 4096; i += 256) {
        int r = i >> 6, c = i & 63;
        sx[c * 68 + r] = __ldg(x + (pt0 + r) * 64 + c);
    }

    int m0 = (t & 15) * 4;
    int n0 = (t >> 4) * 4;

    for (int sect = 0; sect < 5; sect++) {
        __syncthreads();
        for (int i = t; i < 4096; i += 256) {
            float v;
            if      (sect == 0) v = __ldg(Wf + i)        - __ldg(Wf + 8192 + i);
            else if (sect == 1) v = __ldg(Wf + 4096 + i) + __ldg(Wf + 8192 + i);
            else if (sect == 2) v = __ldg(Wm1 + 4096 + i);
            else if (sect == 3) v = __ldg(Wm2 + 8192 + i);
            else                v = __ldg(Wl + 12288 + i);
            sw[i] = v;
        }
        __syncthreads();

        float acc[4][4];
#pragma unroll
        for (int a = 0; a < 4; a++)
#pragma unroll
            for (int bq = 0; bq < 4; bq++) acc[a][bq] = 0.0f;

#pragma unroll 4
        for (int k = 0; k < 64; k++) {
            float4 av = *(const float4*)(sx + k * 68 + m0);
            float4 wv = *(const float4*)(sw + k * 64 + n0);
            float aa[4] = {av.x, av.y, av.z, av.w};
            float ww[4] = {wv.x, wv.y, wv.z, wv.w};
#pragma unroll
            for (int mi = 0; mi < 4; mi++)
#pragma unroll
                for (int ni = 0; ni < 4; ni++)
                    acc[mi][ni] = fmaf(aa[mi], ww[ni], acc[mi][ni]);
        }

        float4 bb = make_float4(0.f, 0.f, 0.f, 0.f);
        const float* bp = (sect == 0) ? bf : (sect == 2) ? bm1
                         : (sect == 3) ? bm2 : (sect == 4) ? bl : nullptr;
        if (bp) bb = __ldg((const float4*)(bp + n0));

#pragma unroll
        for (int mi = 0; mi < 4; mi++) {
            int pt = pt0 + m0 + mi;
            float4 o = make_float4(acc[mi][0] + bb.x, acc[mi][1] + bb.y,
                                   acc[mi][2] + bb.z, acc[mi][3] + bb.w);
            float* dst;
            if (sect == 1) dst = g_Q + pt * 64 + n0;
            else {
                int off = (sect == 0) ? 0 : (sect == 2) ? 64 : (sect == 3) ? 128 : 192;
                dst = g_L + pt * 256 + off + n0;
            }
            *(float4*)dst = o;
        }
    }
}

// ---------------------------------------------------------------------------
// Main edge-MLP + max kernel. Persistent blocks, one per SM.
// Per group: 8 points x 16 edges = 128 edges (M), channels 64 (N).
// Smem H layout (transposed, row = channel, col = edge), rows contiguous:
//   rows [0:64)    = H3
//   rows [64:128)  = H2
//   rows [128:192) = H1
// so step3 consumes rows 64:192 (K=128) and step4 rows 0:192 (K=192) directly.
// ---------------------------------------------------------------------------
template <int KD>
__device__ __forceinline__ void gemm_acc(const float* __restrict__ a,
                                         const float* __restrict__ w,
                                         int m0, int n0, float acc[8][4]) {
#pragma unroll 4
    for (int k = 0; k < KD; k++) {
        float4 a0 = *(const float4*)(a + k * PAD + m0);
        float4 a1 = *(const float4*)(a + k * PAD + m0 + 4);
        float4 wv = *(const float4*)(w + k * 64 + n0);
        float av[8] = {a0.x, a0.y, a0.z, a0.w, a1.x, a1.y, a1.z, a1.w};
        float ww[4] = {wv.x, wv.y, wv.z, wv.w};
#pragma unroll
        for (int mi = 0; mi < 8; mi++)
#pragma unroll
            for (int ni = 0; ni < 4; ni++)
                acc[mi][ni] = fmaf(av[mi], ww[ni], acc[mi][ni]);
    }
}

__device__ __forceinline__ void store_relu_t(const float acc[8][4], float4 r,
                                             float* dstBase, int m0, int n0) {
    float rr[4] = {r.x, r.y, r.z, r.w};
#pragma unroll
    for (int ni = 0; ni < 4; ni++) {
        float4 lo = make_float4(fmaxf(acc[0][ni] + rr[ni], 0.f),
                                fmaxf(acc[1][ni] + rr[ni], 0.f),
                                fmaxf(acc[2][ni] + rr[ni], 0.f),
                                fmaxf(acc[3][ni] + rr[ni], 0.f));
        float4 hi = make_float4(fmaxf(acc[4][ni] + rr[ni], 0.f),
                                fmaxf(acc[5][ni] + rr[ni], 0.f),
                                fmaxf(acc[6][ni] + rr[ni], 0.f),
                                fmaxf(acc[7][ni] + rr[ni], 0.f));
        *(float4*)(dstBase + (n0 + ni) * PAD + m0)     = lo;
        *(float4*)(dstBase + (n0 + ni) * PAD + m0 + 4) = hi;
    }
}

__global__ __launch_bounds__(256, 1) void edge_mlp_kernel(
    const float* __restrict__ x,
    const float* __restrict__ Wm1,  // uses first 64 rows (4096 floats)
    const float* __restrict__ Wm2,  // uses first 128 rows (8192 floats)
    const float* __restrict__ Wl,   // uses first 192 rows (12288 floats)
    float* __restrict__ out) {

    extern __shared__ float smem[];
    float* s_w  = smem;                       // 24576 floats
    float* s_h  = smem + MAIN_W_FLOATS;       // 192*PAD floats
    int*   s_id = (int*)(smem + MAIN_W_FLOATS + MAIN_H_FLOATS);  // 128 ints

    int t = threadIdx.x;

    // Load weight prefixes (rows multiplying the dense H features) into smem.
    for (int i = t; i < 1024; i += 256)
        ((float4*)s_w)[i] = __ldg((const float4*)Wm1 + i);
    for (int i = t; i < 2048; i += 256)
        ((float4*)(s_w + 4096))[i] = __ldg((const float4*)Wm2 + i);
    for (int i = t; i < 3072; i += 256)
        ((float4*)(s_w + 12288))[i] = __ldg((const float4*)Wl + i);
    __syncthreads();

    const int m0 = (t & 15) * 8;       // 8 edges per thread
    const int n0 = (t >> 4) * 4;       // 4 output channels per thread
    const int p_local = (t & 15) >> 1; // point owning this thread's edges

    for (int g = blockIdx.x; g < NGROUPS; g += gridDim.x) {
        int ptg0 = g * 8;
        int b    = ptg0 >> 12;         // batch (group never crosses batch: 8 | 4096)

        if (t < 128) s_id[t] = g_idx[ptg0 * KNN + t];
        __syncthreads();

        // ---- Gather: H1[c][m] = relu(P[pt][c] + Q[nbr][c]) ----
        for (int i = t; i < 2048; i += 256) {
            int m  = i & 127;
            int cq = i >> 7;           // channel quad 0..15
            int j  = s_id[m];
            int pt = ptg0 + (m >> 4);
            float4 qv = __ldg((const float4*)(g_Q + ((b << 12) + j) * 64 + cq * 4));
            float4 pv = __ldg((const float4*)(g_L + pt * 256 + cq * 4));
            float* hb = s_h + (128 + cq * 4) * PAD + m;
            hb[0 * PAD] = fmaxf(pv.x + qv.x, 0.f);
            hb[1 * PAD] = fmaxf(pv.y + qv.y, 0.f);
            hb[2 * PAD] = fmaxf(pv.z + qv.z, 0.f);
            hb[3 * PAD] = fmaxf(pv.w + qv.w, 0.f);
        }
        __syncthreads();

        int ptg = ptg0 + p_local;

        // ---- Step 2: H2 = relu(H1 @ Ws2 + R1) ----
        {
            float acc[8][4];
#pragma unroll
            for (int a = 0; a < 8; a++)
#pragma unroll
                for (int bq = 0; bq < 4; bq++) acc[a][bq] = 0.f;
            gemm_acc<64>(s_h + 128 * PAD, s_w, m0, n0, acc);
            float4 r = __ldg((const float4*)(g_L + ptg * 256 + 64 + n0));
            store_relu_t(acc, r, s_h + 64 * PAD, m0, n0);
        }
        __syncthreads();

        // ---- Step 3: H3 = relu([H2|H1] @ Ws3 + R2) ----
        {
            float acc[8][4];
#pragma unroll
            for (int a = 0; a < 8; a++)
#pragma unroll
                for (int bq = 0; bq < 4; bq++) acc[a][bq] = 0.f;
            gemm_acc<128>(s_h + 64 * PAD, s_w + 4096, m0, n0, acc);
            float4 r = __ldg((const float4*)(g_L + ptg * 256 + 128 + n0));
            store_relu_t(acc, r, s_h, m0, n0);
        }
        __syncthreads();

        // ---- Step 4: H4 = [H3|H2|H1] @ Ws4 + R3 (no relu), fused max over K ----
        {
            float acc[8][4];
#pragma unroll
            for (int a = 0; a < 8; a++)
#pragma unroll
                for (int bq = 0; bq < 4; bq++) acc[a][bq] = 0.f;
            gemm_acc<192>(s_h, s_w + 12288, m0, n0, acc);
            float4 r3 = __ldg((const float4*)(g_L + ptg * 256 + 192 + n0));
            float vmax[4];
#pragma unroll
            for (int ni = 0; ni < 4; ni++) {
                float v = acc[0][ni];
#pragma unroll
                for (int mi = 1; mi < 8; mi++) v = fmaxf(v, acc[mi][ni]);
                vmax[ni] = v;
            }
            vmax[0] += r3.x; vmax[1] += r3.y; vmax[2] += r3.z; vmax[3] += r3.w;
#pragma unroll
            for (int ni = 0; ni < 4; ni++)
                vmax[ni] = fmaxf(vmax[ni], __shfl_xor_sync(0xffffffffu, vmax[ni], 1));
            if ((t & 1) == 0)
                *(float4*)(out + ptg * 320 + n0) =
                    make_float4(vmax[0], vmax[1], vmax[2], vmax[3]);
        }

        // ---- Max over K for H3/H2/H1 directly from smem ----
        for (int i = t; i < 1536; i += 256) {
            int p   = i / 192;
            int row = i - p * 192;
            const float* hp = s_h + row * PAD + p * 16;
            float v = hp[0];
#pragma unroll
            for (int k2 = 1; k2 < 16; k2++) v = fmaxf(v, hp[k2]);
            out[(ptg0 + p) * 320 + 64 + row] = v;  // H3->64:128, H2->128:192, H1->192:256
        }

        // ---- x passthrough: max over K of constant x is x ----
        for (int i = t; i < 512; i += 256) {
            int p = i >> 6, c = i & 63;
            out[(ptg0 + p) * 320 + 256 + c] = __ldg(x + (ptg0 + p) * 64 + c);
        }
        __syncthreads();   // protect s_h before next group's gather
    }
}

// ---------------------------------------------------------------------------
extern "C" void kernel_launch(void* const* d_in, const int* in_sizes, int n_in,
                              void* d_out, int out_size) {
    const float* x   = (const float*)d_in[0];
    const float* pos = (const float*)d_in[1];
    const float* Wf  = (const float*)d_in[2];
    const float* bf  = (const float*)d_in[3];
    const float* Wm1 = (const float*)d_in[4];
    const float* bm1 = (const float*)d_in[5];
    const float* Wm2 = (const float*)d_in[6];
    const float* bm2 = (const float*)d_in[7];
    const float* Wl  = (const float*)d_in[8];
    const float* bl  = (const float*)d_in[9];
    float* out = (float*)d_out;

    cudaFuncSetAttribute(edge_mlp_kernel,
                         cudaFuncAttributeMaxDynamicSharedMemorySize,
                         MAIN_SMEM_BYTES);

    knn_kernel<<<128, 128>>>(pos);
    pre_kernel<<<256, 256>>>(x, Wf, bf, Wm1, bm1, Wm2, bm2, Wl, bl);
    edge_mlp_kernel<<<148, 256, MAIN_SMEM_BYTES>>>(x, Wm1, Wm2, Wl, out);
}